// round 8
// baseline (speedup 1.0000x reference)
#include <cuda_runtime.h>
#include <cuda_fp16.h>
#include <cstdint>

// ---------------------------------------------------------------------------
// VQ-VAE vector quantizer, GB300 sm_103a (sm_103-generic toolchain).
// R6 baseline (164us) + single change: k_mma chunk loop order
// mma -> sync -> issue(c+2) -> fold  (fold overlaps cp.async stream),
// keeping unroll 2 (R7's unroll 4 caused spills: 164->242 regression).
// ---------------------------------------------------------------------------

#define N_ROWS   32768
#define K_CODES  1024
#define D_DIM    256

#define OFF_LOSS 8388608
#define OFF_IDX  8388609
#define OFF_EMB  8421377
#define OFF_CS   8683521
#define OFF_ES   8684545

#define THETA    2.5e-4f

__device__ float   g_enorm[K_CODES];
__device__ int     g_indices[N_ROWS];
__device__ float   g_counts[K_CODES];
__device__ float4  g_embed_sum4[K_CODES * 64];
__device__ __half  g_E16[K_CODES * D_DIM];
__device__ int     g_cn[N_ROWS];
__device__ int     g_cand[N_ROWS * 24];
__device__ int     g_nc;
__device__ float   g_loss_sc;
__device__ float   g_loss_zn;

// ---------------- helpers --------------------------------------------------
__device__ __forceinline__ uint32_t smem_to_u32(const void* p) {
    uint32_t a;
    asm("{ .reg .u64 t; cvta.to.shared.u64 t, %1; cvt.u32.u64 %0, t; }"
        : "=r"(a) : "l"(p));
    return a;
}

__device__ __forceinline__ void ldm4(uint32_t r[4], uint32_t addr) {
    asm volatile("ldmatrix.sync.aligned.m8n8.x4.shared.b16 {%0,%1,%2,%3}, [%4];"
                 : "=r"(r[0]), "=r"(r[1]), "=r"(r[2]), "=r"(r[3]) : "r"(addr));
}

__device__ __forceinline__ void mma16816(float c[4], const uint32_t a[4],
                                         uint32_t b0, uint32_t b1) {
    asm volatile(
        "mma.sync.aligned.m16n8k16.row.col.f32.f16.f16.f32 "
        "{%0,%1,%2,%3}, {%4,%5,%6,%7}, {%8,%9}, {%0,%1,%2,%3};"
        : "+f"(c[0]), "+f"(c[1]), "+f"(c[2]), "+f"(c[3])
        : "r"(a[0]), "r"(a[1]), "r"(a[2]), "r"(a[3]), "r"(b0), "r"(b1));
}

// ---------------------------------------------------------------------------
// Kernel 1: ||e||^2, E -> fp16, zero scratch
// ---------------------------------------------------------------------------
__global__ void k_init(const float* __restrict__ E, float* __restrict__ out) {
    const int k = blockIdx.x;
    const int t = threadIdx.x;
    float v = E[k * D_DIM + t];
    g_E16[k * D_DIM + t] = __float2half_rn(v);
    float s = v * v;
    #pragma unroll
    for (int o = 16; o; o >>= 1) s += __shfl_down_sync(0xffffffffu, s, o);
    __shared__ float ws[8];
    if ((t & 31) == 0) ws[t >> 5] = s;
    __syncthreads();
    if (t == 0) {
        float tot = 0.f;
        #pragma unroll
        for (int i = 0; i < 8; ++i) tot += ws[i];
        g_enorm[k]  = tot;
        g_counts[k] = 0.f;
        if (k == 0) { g_nc = 0; g_loss_sc = 0.f; g_loss_zn = 0.f; }
    }
    ((float*)g_embed_sum4)[k * 256 + t] = 0.f;
}

// ---------------------------------------------------------------------------
// Kernel 2: fp16 mma.sync GEMM (128 rows/CTA x 1024 codes, D=256).
// 8 warps: 4(m) x 2(n). Per-thread top-3 per row-slot over its code partition.
// ---------------------------------------------------------------------------
#define SM_A   0
#define SM_B   65536
#define SM_EN  196608
#define SM_RED SM_B
#define SMEM_MMA_TOTAL 200704

__global__ __launch_bounds__(256, 1)
void k_mma(const float* __restrict__ z, float* __restrict__ out) {
    extern __shared__ char smem[];
    const uint32_t sb = smem_to_u32(smem);
    const int tid  = threadIdx.x;
    const int warp = tid >> 5;
    const int lane = tid & 31;
    const int n0  = blockIdx.x * 128;
    const int b   = n0 >> 10;
    const int hw0 = n0 & 1023;

    // ---- prologue: A tile (z rows -> fp16, swizzled row-major [row][d]) ----
    const float4* zb4 = (const float4*)(z + (size_t)b * 262144 + hw0);
    #pragma unroll 4
    for (int i = 0; i < 16; ++i) {
        int f  = i * 256 + tid;
        int d2 = f >> 5;
        int r4 = f & 31;
        float4 v0 = zb4[(2 * d2) * 256 + r4];
        float4 v1 = zb4[(2 * d2 + 1) * 256 + r4];
        float a0[4] = {v0.x, v0.y, v0.z, v0.w};
        float a1[4] = {v1.x, v1.y, v1.z, v1.w};
        #pragma unroll
        for (int j = 0; j < 4; ++j) {
            int row = r4 * 4 + j;
            uint32_t off = ((uint32_t)row << 9) | ((uint32_t)d2 << 2);
            off ^= (uint32_t)(row & 7) << 4;
            *(__half2*)(smem + off) = __floats2half2_rn(a0[j], a1[j]);
        }
    }
    float* s_en = (float*)(smem + SM_EN);
    #pragma unroll
    for (int i = 0; i < 4; ++i) s_en[tid + i * 256] = g_enorm[tid + i * 256];

    auto issue = [&](int c) {
        const __half* src = g_E16 + (size_t)c * 128 * 256;
        const uint32_t base = sb + SM_B + (uint32_t)(c & 1) * 65536;
        #pragma unroll
        for (int i = 0; i < 16; ++i) {
            int lin  = tid + i * 256;
            int code = lin >> 5, d8 = lin & 31;
            uint32_t off = ((uint32_t)code << 9) + ((uint32_t)d8 << 4);
            off ^= (uint32_t)(code & 7) << 4;
            const void* g = src + code * 256 + d8 * 8;
            asm volatile("cp.async.cg.shared.global [%0], [%1], 16;"
                         :: "r"(base + off), "l"(g));
        }
        asm volatile("cp.async.commit_group;" ::: "memory");
    };
    issue(0);
    issue(1);
    __syncthreads();

    const int mw = warp & 3;
    const int nc = warp >> 2;
    const int mat = lane >> 3, rwi = lane & 7;

    uint32_t aBase[2], aXor[2];
    #pragma unroll
    for (int mt = 0; mt < 2; ++mt) {
        int row = mw * 32 + mt * 16 + rwi + ((mat & 1) << 3);
        aBase[mt] = sb + ((uint32_t)row << 9);
        aXor[mt]  = (uint32_t)(row & 7) << 4;
    }
    const uint32_t aK = (uint32_t)(mat >> 1) << 4;

    uint32_t bBase[4], bXor[4];
    #pragma unroll
    for (int np = 0; np < 4; ++np) {
        int code = nc * 64 + np * 16 + rwi + ((mat >> 1) << 3);
        bBase[np] = ((uint32_t)code << 9);
        bXor[np]  = (uint32_t)(code & 7) << 4;
    }
    const uint32_t bK = (uint32_t)(mat & 1) << 4;

    float b1[4], b2[4], b3[4];
    int   i1[4], i2[4], i3[4];
    #pragma unroll
    for (int l = 0; l < 4; ++l) {
        b1[l] = b2[l] = b3[l] = 3.4e38f;
        i1[l] = i2[l] = i3[l] = 0;
    }

    for (int c = 0; c < 8; ++c) {
        if (c == 7) asm volatile("cp.async.wait_group 0;" ::: "memory");
        else        asm volatile("cp.async.wait_group 1;" ::: "memory");
        __syncthreads();

        const uint32_t bBuf = sb + SM_B + (uint32_t)(c & 1) * 65536;
        float acc[2][8][4];
        #pragma unroll
        for (int mt = 0; mt < 2; ++mt)
            #pragma unroll
            for (int nt = 0; nt < 8; ++nt)
                #pragma unroll
                for (int q = 0; q < 4; ++q) acc[mt][nt][q] = 0.f;

        #pragma unroll 2
        for (int ks = 0; ks < 16; ++ks) {
            const uint32_t kb = (uint32_t)ks << 5;
            uint32_t af[2][4], bf[4][4];
            #pragma unroll
            for (int mt = 0; mt < 2; ++mt)
                ldm4(af[mt], aBase[mt] + ((kb + aK) ^ aXor[mt]));
            #pragma unroll
            for (int np = 0; np < 4; ++np)
                ldm4(bf[np], bBuf + bBase[np] + ((kb + bK) ^ bXor[np]));
            #pragma unroll
            for (int mt = 0; mt < 2; ++mt)
                #pragma unroll
                for (int np = 0; np < 4; ++np) {
                    mma16816(acc[mt][np * 2],     af[mt], bf[np][0], bf[np][1]);
                    mma16816(acc[mt][np * 2 + 1], af[mt], bf[np][2], bf[np][3]);
                }
        }

        // buf (c&1) fully consumed -> start chunk c+2 loads, fold overlaps.
        __syncthreads();
        if (c + 2 < 8) issue(c + 2);

        #pragma unroll
        for (int mt = 0; mt < 2; ++mt)
            #pragma unroll
            for (int nt = 0; nt < 8; ++nt) {
                int code = c * 128 + nc * 64 + nt * 8 + (lane & 3) * 2;
                float en0 = s_en[code], en1 = s_en[code + 1];
                #pragma unroll
                for (int h = 0; h < 2; ++h) {
                    int l = mt * 2 + h;
                    float sc0 = fmaf(-2.0f, acc[mt][nt][h * 2],     en0);
                    float sc1 = fmaf(-2.0f, acc[mt][nt][h * 2 + 1], en1);
                    if (sc0 < b3[l]) {
                        if (sc0 < b1[l]) {
                            b3[l]=b2[l]; i3[l]=i2[l]; b2[l]=b1[l]; i2[l]=i1[l];
                            b1[l]=sc0;   i1[l]=code;
                        } else if (sc0 < b2[l]) {
                            b3[l]=b2[l]; i3[l]=i2[l]; b2[l]=sc0; i2[l]=code;
                        } else { b3[l]=sc0; i3[l]=code; }
                    }
                    if (sc1 < b3[l]) {
                        if (sc1 < b1[l]) {
                            b3[l]=b2[l]; i3[l]=i2[l]; b2[l]=b1[l]; i2[l]=i1[l];
                            b1[l]=sc1;   i1[l]=code + 1;
                        } else if (sc1 < b2[l]) {
                            b3[l]=b2[l]; i3[l]=i2[l]; b2[l]=sc1; i2[l]=code + 1;
                        } else { b3[l]=sc1; i3[l]=code + 1; }
                    }
                }
            }
    }

    // ---- row reduce over 8 partitions x top-3 ----
    __syncthreads();
    float* rb1 = (float*)(smem + SM_RED);
    float* rb2 = (float*)(smem + SM_RED + 4096);
    float* rb3 = (float*)(smem + SM_RED + 8192);
    int*   ri1 = (int*)  (smem + SM_RED + 12288);
    int*   ri2 = (int*)  (smem + SM_RED + 16384);
    int*   ri3 = (int*)  (smem + SM_RED + 20480);
    float* lws = (float*)(smem + SM_RED + 24576);
    const int slot = nc * 4 + (lane & 3);
    #pragma unroll
    for (int l = 0; l < 4; ++l) {
        int R = mw * 32 + (l >> 1) * 16 + (l & 1) * 8 + (lane >> 2);
        rb1[R * 8 + slot] = b1[l]; ri1[R * 8 + slot] = i1[l];
        rb2[R * 8 + slot] = b2[l]; ri2[R * 8 + slot] = i2[l];
        rb3[R * 8 + slot] = b3[l]; ri3[R * 8 + slot] = i3[l];
    }
    __syncthreads();

    float lsum = 0.f;
    if (tid < 128) {
        float B1 = 3.4e38f, B2 = 3.4e38f;
        int I1 = 0x7fffffff;
        #pragma unroll
        for (int s = 0; s < 8; ++s) {
            int base = tid * 8 + s;
            float v; int iv;
            v = rb1[base]; iv = ri1[base];
            if (v < B1 || (v == B1 && iv < I1)) { B2 = B1; B1 = v; I1 = iv; }
            else if (v < B2) B2 = v;
            v = rb2[base]; iv = ri2[base];
            if (v < B1 || (v == B1 && iv < I1)) { B2 = B1; B1 = v; I1 = iv; }
            else if (v < B2) B2 = v;
            v = rb3[base]; iv = ri3[base];
            if (v < B1 || (v == B1 && iv < I1)) { B2 = B1; B1 = v; I1 = iv; }
            else if (v < B2) B2 = v;
        }
        const int n = n0 + tid;
        g_indices[n] = I1;
        out[(size_t)OFF_IDX + n] = (float)I1;
        lsum = B1;
        if (B2 - B1 < THETA) {
            int p = atomicAdd(&g_nc, 1);
            g_cn[p] = n;
            #pragma unroll
            for (int s = 0; s < 8; ++s) {
                int base = tid * 8 + s;
                g_cand[p * 24 + s * 3 + 0] = ri1[base];
                g_cand[p * 24 + s * 3 + 1] = ri2[base];
                g_cand[p * 24 + s * 3 + 2] = ri3[base];
            }
        }
    }
    #pragma unroll
    for (int o = 16; o; o >>= 1) lsum += __shfl_down_sync(0xffffffffu, lsum, o);
    if (lane == 0) lws[warp] = lsum;
    __syncthreads();
    if (tid == 0) {
        float tot = 0.f;
        #pragma unroll
        for (int i = 0; i < 8; ++i) tot += lws[i];
        atomicAdd(&g_loss_sc, tot);
    }
}

// ---------------------------------------------------------------------------
// Kernel 3: warp-per-row exact rescue over 24 candidates (4-wide batches).
// ---------------------------------------------------------------------------
__global__ __launch_bounds__(256)
void k_fix(const float* __restrict__ z, const float* __restrict__ E,
           float* __restrict__ out) {
    const int cnt = g_nc;
    const int lane = threadIdx.x & 31;
    const int gw = (blockIdx.x * blockDim.x + threadIdx.x) >> 5;
    const int nw = (gridDim.x * blockDim.x) >> 5;

    for (int r = gw; r < cnt; r += nw) {
        const int n = g_cn[r];
        const int b = n >> 10, pos = n & 1023;
        const float* zr = z + (size_t)b * 262144 + pos;
        float zv[8];
        #pragma unroll
        for (int i = 0; i < 8; ++i)
            zv[i] = zr[(size_t)(lane + 32 * i) * 1024];
        double za = 0.0;
        #pragma unroll
        for (int i = 0; i < 8; ++i) za += (double)zv[i] * zv[i];
        #pragma unroll
        for (int o = 16; o; o >>= 1)
            za += __shfl_xor_sync(0xffffffffu, za, o);
        const float zn = (float)za;

        float bd = 3.4e38f;
        int   bi = 0x7fffffff;
        #pragma unroll 1
        for (int jb = 0; jb < 24; jb += 4) {
            int kc[4];
            float ac[4] = {0.f, 0.f, 0.f, 0.f};
            #pragma unroll
            for (int q = 0; q < 4; ++q) kc[q] = g_cand[r * 24 + jb + q];
            #pragma unroll
            for (int i = 0; i < 8; ++i) {
                #pragma unroll
                for (int q = 0; q < 4; ++q)
                    ac[q] = fmaf(zv[i], E[(size_t)kc[q] * 256 + lane + 32 * i],
                                 ac[q]);
            }
            #pragma unroll
            for (int o = 16; o; o >>= 1) {
                #pragma unroll
                for (int q = 0; q < 4; ++q)
                    ac[q] += __shfl_xor_sync(0xffffffffu, ac[q], o);
            }
            #pragma unroll
            for (int q = 0; q < 4; ++q) {
                float di = (zn - 2.0f * ac[q]) + g_enorm[kc[q]];
                if (di < bd || (di == bd && kc[q] < bi)) { bd = di; bi = kc[q]; }
            }
        }
        if (lane == 0) {
            g_indices[n] = bi;
            out[(size_t)OFF_IDX + n] = (float)bi;
        }
    }
}

// ---------------------------------------------------------------------------
// Kernel 4: fused gather/scatter (R6 staging version, 35us).
// z_q_st = fl(z + fl(E[idx]-z)), ||z||^2 partial, float4 RED scatter, counts.
// ---------------------------------------------------------------------------
__global__ __launch_bounds__(256)
void k_gather(const float* __restrict__ z, const float* __restrict__ E,
              float* __restrict__ out) {
    __shared__ float es[32 * 260];
    __shared__ int   sidx[32];
    __shared__ float ws[8];
    const int t   = threadIdx.x;
    const int n0  = blockIdx.x * 32;     // grid 1024
    const int b   = n0 >> 10;
    const int rem = n0 & 1023;

    if (t < 32) {
        int k = g_indices[n0 + t];
        sidx[t] = k;
        atomicAdd(&g_counts[k], 1.0f);
    }
    __syncthreads();

    #pragma unroll
    for (int k = 0; k < 32; ++k)
        es[k * 260 + t] = E[(size_t)sidx[k] * 256 + t];
    __syncthreads();

    const float* zb = z   + (size_t)b * 262144 + rem;
    float*       qb = out + (size_t)b * 262144 + rem;

    float zs = 0.f;
    #pragma unroll 2
    for (int it = 0; it < 8; ++it) {
        int idx = t + it * 256;          // 0..2047
        int nl  = idx & 31;
        int d4  = idx >> 5;              // 0..63
        int d   = d4 << 2;
        float4 e = *(const float4*)&es[nl * 260 + d];
        float z0 = zb[(size_t)(d + 0) * 1024 + nl];
        float z1 = zb[(size_t)(d + 1) * 1024 + nl];
        float z2 = zb[(size_t)(d + 2) * 1024 + nl];
        float z3 = zb[(size_t)(d + 3) * 1024 + nl];
        qb[(size_t)(d + 0) * 1024 + nl] = z0 + (e.x - z0);
        qb[(size_t)(d + 1) * 1024 + nl] = z1 + (e.y - z1);
        qb[(size_t)(d + 2) * 1024 + nl] = z2 + (e.z - z2);
        qb[(size_t)(d + 3) * 1024 + nl] = z3 + (e.w - z3);
        zs += z0 * z0 + z1 * z1 + z2 * z2 + z3 * z3;
        atomicAdd(&g_embed_sum4[(size_t)sidx[nl] * 64 + d4],
                  make_float4(z0, z1, z2, z3));
    }
    #pragma unroll
    for (int o = 16; o; o >>= 1) zs += __shfl_down_sync(0xffffffffu, zs, o);
    if ((t & 31) == 0) ws[t >> 5] = zs;
    __syncthreads();
    if (t == 0) {
        float tot = 0.f;
        #pragma unroll
        for (int i = 0; i < 8; ++i) tot += ws[i];
        atomicAdd(&g_loss_zn, tot);
    }
}

// ---------------------------------------------------------------------------
// Kernel 5: merged EMA epilogue.
// ---------------------------------------------------------------------------
__global__ __launch_bounds__(1024)
void k_emb(const float* __restrict__ cs_in, const float* __restrict__ es_in,
           float* __restrict__ out) {
    __shared__ float s_n;
    const int tid = threadIdx.x;
    const int i = blockIdx.x * 1024 + tid;   // grid 256 -> 262144

    if (tid < 32) {
        float s = 0.f;
        #pragma unroll
        for (int j = 0; j < 32; ++j) s += cs_in[tid + j * 32];
        #pragma unroll
        for (int o = 16; o; o >>= 1) s += __shfl_xor_sync(0xffffffffu, s, o);
        if (tid == 0) s_n = 0.99f * s + 327.68f;
    }
    __syncthreads();

    const int k = i >> 8;
    float c = 0.99f * cs_in[k] + 0.01f * g_counts[k];
    if ((i & 255) == 0) out[(size_t)OFF_CS + k] = c;
    float n  = s_n;
    float cl = (c + 1e-5f) / (n + 0.01024f) * n;
    float es = 0.99f * es_in[i] + 0.01f * ((const float*)g_embed_sum4)[i];
    out[(size_t)OFF_ES  + i] = es;
    out[(size_t)OFF_EMB + i] = es / cl;
    if (i == 0)
        out[OFF_LOSS] = (g_loss_zn + g_loss_sc) * (1.0f / 8388608.0f);
}

// ---------------------------------------------------------------------------
extern "C" void kernel_launch(void* const* d_in, const int* in_sizes, int n_in,
                              void* d_out, int out_size) {
    const float* z  = (const float*)d_in[0];
    const float* E  = (const float*)d_in[1];
    const float* cs = (const float*)d_in[2];
    const float* es = (const float*)d_in[3];
    float* out = (float*)d_out;

    cudaFuncSetAttribute(k_mma, cudaFuncAttributeMaxDynamicSharedMemorySize,
                         SMEM_MMA_TOTAL);

    k_init  <<<1024, 256>>>(E, out);
    k_mma   <<< 256, 256, SMEM_MMA_TOTAL>>>(z, out);
    k_fix   <<< 128, 256>>>(z, E, out);
    k_gather<<<1024, 256>>>(z, E, out);
    k_emb   <<< 256, 1024>>>(cs, es, out);
}

// round 10
// speedup vs baseline: 1.6309x; 1.6309x over previous
#include <cuda_runtime.h>
#include <cuda_fp16.h>
#include <cstdint>

// ---------------------------------------------------------------------------
// VQ-VAE vector quantizer, GB300 sm_103a (sm_103-generic toolchain).
// R6 baseline restored exactly (fold BEFORE sync/issue: fold consumes the 64
// acc regs before the cp.async issue block, avoiding the R7/R8 spill).
// Only change: k_fix grid 128 -> 256.
// ---------------------------------------------------------------------------

#define N_ROWS   32768
#define K_CODES  1024
#define D_DIM    256

#define OFF_LOSS 8388608
#define OFF_IDX  8388609
#define OFF_EMB  8421377
#define OFF_CS   8683521
#define OFF_ES   8684545

#define THETA    2.5e-4f

__device__ float   g_enorm[K_CODES];
__device__ int     g_indices[N_ROWS];
__device__ float   g_counts[K_CODES];
__device__ float4  g_embed_sum4[K_CODES * 64];
__device__ __half  g_E16[K_CODES * D_DIM];
__device__ int     g_cn[N_ROWS];
__device__ int     g_cand[N_ROWS * 24];
__device__ int     g_nc;
__device__ float   g_loss_sc;
__device__ float   g_loss_zn;

// ---------------- helpers --------------------------------------------------
__device__ __forceinline__ uint32_t smem_to_u32(const void* p) {
    uint32_t a;
    asm("{ .reg .u64 t; cvta.to.shared.u64 t, %1; cvt.u32.u64 %0, t; }"
        : "=r"(a) : "l"(p));
    return a;
}

__device__ __forceinline__ void ldm4(uint32_t r[4], uint32_t addr) {
    asm volatile("ldmatrix.sync.aligned.m8n8.x4.shared.b16 {%0,%1,%2,%3}, [%4];"
                 : "=r"(r[0]), "=r"(r[1]), "=r"(r[2]), "=r"(r[3]) : "r"(addr));
}

__device__ __forceinline__ void mma16816(float c[4], const uint32_t a[4],
                                         uint32_t b0, uint32_t b1) {
    asm volatile(
        "mma.sync.aligned.m16n8k16.row.col.f32.f16.f16.f32 "
        "{%0,%1,%2,%3}, {%4,%5,%6,%7}, {%8,%9}, {%0,%1,%2,%3};"
        : "+f"(c[0]), "+f"(c[1]), "+f"(c[2]), "+f"(c[3])
        : "r"(a[0]), "r"(a[1]), "r"(a[2]), "r"(a[3]), "r"(b0), "r"(b1));
}

// ---------------------------------------------------------------------------
// Kernel 1: ||e||^2, E -> fp16, zero scratch
// ---------------------------------------------------------------------------
__global__ void k_init(const float* __restrict__ E, float* __restrict__ out) {
    const int k = blockIdx.x;
    const int t = threadIdx.x;
    float v = E[k * D_DIM + t];
    g_E16[k * D_DIM + t] = __float2half_rn(v);
    float s = v * v;
    #pragma unroll
    for (int o = 16; o; o >>= 1) s += __shfl_down_sync(0xffffffffu, s, o);
    __shared__ float ws[8];
    if ((t & 31) == 0) ws[t >> 5] = s;
    __syncthreads();
    if (t == 0) {
        float tot = 0.f;
        #pragma unroll
        for (int i = 0; i < 8; ++i) tot += ws[i];
        g_enorm[k]  = tot;
        g_counts[k] = 0.f;
        if (k == 0) { g_nc = 0; g_loss_sc = 0.f; g_loss_zn = 0.f; }
    }
    ((float*)g_embed_sum4)[k * 256 + t] = 0.f;
}

// ---------------------------------------------------------------------------
// Kernel 2: fp16 mma.sync GEMM (128 rows/CTA x 1024 codes, D=256).
// 8 warps: 4(m) x 2(n). Per-thread top-3 per row-slot over its code partition.
// Chunk order: mma -> fold -> sync -> issue(c+2). DO NOT move the fold after
// issue: acc[64] must die in the fold before the issue block (R7/R8 spills).
// ---------------------------------------------------------------------------
#define SM_A   0
#define SM_B   65536
#define SM_EN  196608
#define SM_RED SM_B
#define SMEM_MMA_TOTAL 200704

__global__ __launch_bounds__(256, 1)
void k_mma(const float* __restrict__ z, float* __restrict__ out) {
    extern __shared__ char smem[];
    const uint32_t sb = smem_to_u32(smem);
    const int tid  = threadIdx.x;
    const int warp = tid >> 5;
    const int lane = tid & 31;
    const int n0  = blockIdx.x * 128;
    const int b   = n0 >> 10;
    const int hw0 = n0 & 1023;

    // ---- prologue: A tile (z rows -> fp16, swizzled row-major [row][d]) ----
    const float4* zb4 = (const float4*)(z + (size_t)b * 262144 + hw0);
    #pragma unroll 4
    for (int i = 0; i < 16; ++i) {
        int f  = i * 256 + tid;
        int d2 = f >> 5;
        int r4 = f & 31;
        float4 v0 = zb4[(2 * d2) * 256 + r4];
        float4 v1 = zb4[(2 * d2 + 1) * 256 + r4];
        float a0[4] = {v0.x, v0.y, v0.z, v0.w};
        float a1[4] = {v1.x, v1.y, v1.z, v1.w};
        #pragma unroll
        for (int j = 0; j < 4; ++j) {
            int row = r4 * 4 + j;
            uint32_t off = ((uint32_t)row << 9) | ((uint32_t)d2 << 2);
            off ^= (uint32_t)(row & 7) << 4;
            *(__half2*)(smem + off) = __floats2half2_rn(a0[j], a1[j]);
        }
    }
    float* s_en = (float*)(smem + SM_EN);
    #pragma unroll
    for (int i = 0; i < 4; ++i) s_en[tid + i * 256] = g_enorm[tid + i * 256];

    auto issue = [&](int c) {
        const __half* src = g_E16 + (size_t)c * 128 * 256;
        const uint32_t base = sb + SM_B + (uint32_t)(c & 1) * 65536;
        #pragma unroll
        for (int i = 0; i < 16; ++i) {
            int lin  = tid + i * 256;
            int code = lin >> 5, d8 = lin & 31;
            uint32_t off = ((uint32_t)code << 9) + ((uint32_t)d8 << 4);
            off ^= (uint32_t)(code & 7) << 4;
            const void* g = src + code * 256 + d8 * 8;
            asm volatile("cp.async.cg.shared.global [%0], [%1], 16;"
                         :: "r"(base + off), "l"(g));
        }
        asm volatile("cp.async.commit_group;" ::: "memory");
    };
    issue(0);
    issue(1);
    __syncthreads();

    const int mw = warp & 3;
    const int nc = warp >> 2;
    const int mat = lane >> 3, rwi = lane & 7;

    uint32_t aBase[2], aXor[2];
    #pragma unroll
    for (int mt = 0; mt < 2; ++mt) {
        int row = mw * 32 + mt * 16 + rwi + ((mat & 1) << 3);
        aBase[mt] = sb + ((uint32_t)row << 9);
        aXor[mt]  = (uint32_t)(row & 7) << 4;
    }
    const uint32_t aK = (uint32_t)(mat >> 1) << 4;

    uint32_t bBase[4], bXor[4];
    #pragma unroll
    for (int np = 0; np < 4; ++np) {
        int code = nc * 64 + np * 16 + rwi + ((mat >> 1) << 3);
        bBase[np] = ((uint32_t)code << 9);
        bXor[np]  = (uint32_t)(code & 7) << 4;
    }
    const uint32_t bK = (uint32_t)(mat & 1) << 4;

    float b1[4], b2[4], b3[4];
    int   i1[4], i2[4], i3[4];
    #pragma unroll
    for (int l = 0; l < 4; ++l) {
        b1[l] = b2[l] = b3[l] = 3.4e38f;
        i1[l] = i2[l] = i3[l] = 0;
    }

    for (int c = 0; c < 8; ++c) {
        if (c == 7) asm volatile("cp.async.wait_group 0;" ::: "memory");
        else        asm volatile("cp.async.wait_group 1;" ::: "memory");
        __syncthreads();

        const uint32_t bBuf = sb + SM_B + (uint32_t)(c & 1) * 65536;
        float acc[2][8][4];
        #pragma unroll
        for (int mt = 0; mt < 2; ++mt)
            #pragma unroll
            for (int nt = 0; nt < 8; ++nt)
                #pragma unroll
                for (int q = 0; q < 4; ++q) acc[mt][nt][q] = 0.f;

        #pragma unroll 2
        for (int ks = 0; ks < 16; ++ks) {
            const uint32_t kb = (uint32_t)ks << 5;
            uint32_t af[2][4], bf[4][4];
            #pragma unroll
            for (int mt = 0; mt < 2; ++mt)
                ldm4(af[mt], aBase[mt] + ((kb + aK) ^ aXor[mt]));
            #pragma unroll
            for (int np = 0; np < 4; ++np)
                ldm4(bf[np], bBuf + bBase[np] + ((kb + bK) ^ bXor[np]));
            #pragma unroll
            for (int mt = 0; mt < 2; ++mt)
                #pragma unroll
                for (int np = 0; np < 4; ++np) {
                    mma16816(acc[mt][np * 2],     af[mt], bf[np][0], bf[np][1]);
                    mma16816(acc[mt][np * 2 + 1], af[mt], bf[np][2], bf[np][3]);
                }
        }

        // fold FIRST (consumes acc), then sync, then refill buffer
        #pragma unroll
        for (int mt = 0; mt < 2; ++mt)
            #pragma unroll
            for (int nt = 0; nt < 8; ++nt) {
                int code = c * 128 + nc * 64 + nt * 8 + (lane & 3) * 2;
                float en0 = s_en[code], en1 = s_en[code + 1];
                #pragma unroll
                for (int h = 0; h < 2; ++h) {
                    int l = mt * 2 + h;
                    float sc0 = fmaf(-2.0f, acc[mt][nt][h * 2],     en0);
                    float sc1 = fmaf(-2.0f, acc[mt][nt][h * 2 + 1], en1);
                    if (sc0 < b3[l]) {
                        if (sc0 < b1[l]) {
                            b3[l]=b2[l]; i3[l]=i2[l]; b2[l]=b1[l]; i2[l]=i1[l];
                            b1[l]=sc0;   i1[l]=code;
                        } else if (sc0 < b2[l]) {
                            b3[l]=b2[l]; i3[l]=i2[l]; b2[l]=sc0; i2[l]=code;
                        } else { b3[l]=sc0; i3[l]=code; }
                    }
                    if (sc1 < b3[l]) {
                        if (sc1 < b1[l]) {
                            b3[l]=b2[l]; i3[l]=i2[l]; b2[l]=b1[l]; i2[l]=i1[l];
                            b1[l]=sc1;   i1[l]=code + 1;
                        } else if (sc1 < b2[l]) {
                            b3[l]=b2[l]; i3[l]=i2[l]; b2[l]=sc1; i2[l]=code + 1;
                        } else { b3[l]=sc1; i3[l]=code + 1; }
                    }
                }
            }

        __syncthreads();
        if (c + 2 < 8) issue(c + 2);
    }

    // ---- row reduce over 8 partitions x top-3 ----
    __syncthreads();
    float* rb1 = (float*)(smem + SM_RED);
    float* rb2 = (float*)(smem + SM_RED + 4096);
    float* rb3 = (float*)(smem + SM_RED + 8192);
    int*   ri1 = (int*)  (smem + SM_RED + 12288);
    int*   ri2 = (int*)  (smem + SM_RED + 16384);
    int*   ri3 = (int*)  (smem + SM_RED + 20480);
    float* lws = (float*)(smem + SM_RED + 24576);
    const int slot = nc * 4 + (lane & 3);
    #pragma unroll
    for (int l = 0; l < 4; ++l) {
        int R = mw * 32 + (l >> 1) * 16 + (l & 1) * 8 + (lane >> 2);
        rb1[R * 8 + slot] = b1[l]; ri1[R * 8 + slot] = i1[l];
        rb2[R * 8 + slot] = b2[l]; ri2[R * 8 + slot] = i2[l];
        rb3[R * 8 + slot] = b3[l]; ri3[R * 8 + slot] = i3[l];
    }
    __syncthreads();

    float lsum = 0.f;
    if (tid < 128) {
        float B1 = 3.4e38f, B2 = 3.4e38f;
        int I1 = 0x7fffffff;
        #pragma unroll
        for (int s = 0; s < 8; ++s) {
            int base = tid * 8 + s;
            float v; int iv;
            v = rb1[base]; iv = ri1[base];
            if (v < B1 || (v == B1 && iv < I1)) { B2 = B1; B1 = v; I1 = iv; }
            else if (v < B2) B2 = v;
            v = rb2[base]; iv = ri2[base];
            if (v < B1 || (v == B1 && iv < I1)) { B2 = B1; B1 = v; I1 = iv; }
            else if (v < B2) B2 = v;
            v = rb3[base]; iv = ri3[base];
            if (v < B1 || (v == B1 && iv < I1)) { B2 = B1; B1 = v; I1 = iv; }
            else if (v < B2) B2 = v;
        }
        const int n = n0 + tid;
        g_indices[n] = I1;
        out[(size_t)OFF_IDX + n] = (float)I1;
        lsum = B1;
        if (B2 - B1 < THETA) {
            int p = atomicAdd(&g_nc, 1);
            g_cn[p] = n;
            #pragma unroll
            for (int s = 0; s < 8; ++s) {
                int base = tid * 8 + s;
                g_cand[p * 24 + s * 3 + 0] = ri1[base];
                g_cand[p * 24 + s * 3 + 1] = ri2[base];
                g_cand[p * 24 + s * 3 + 2] = ri3[base];
            }
        }
    }
    #pragma unroll
    for (int o = 16; o; o >>= 1) lsum += __shfl_down_sync(0xffffffffu, lsum, o);
    if (lane == 0) lws[warp] = lsum;
    __syncthreads();
    if (tid == 0) {
        float tot = 0.f;
        #pragma unroll
        for (int i = 0; i < 8; ++i) tot += lws[i];
        atomicAdd(&g_loss_sc, tot);
    }
}

// ---------------------------------------------------------------------------
// Kernel 3: warp-per-row exact rescue over 24 candidates (4-wide batches).
// ---------------------------------------------------------------------------
__global__ __launch_bounds__(256)
void k_fix(const float* __restrict__ z, const float* __restrict__ E,
           float* __restrict__ out) {
    const int cnt = g_nc;
    const int lane = threadIdx.x & 31;
    const int gw = (blockIdx.x * blockDim.x + threadIdx.x) >> 5;
    const int nw = (gridDim.x * blockDim.x) >> 5;

    for (int r = gw; r < cnt; r += nw) {
        const int n = g_cn[r];
        const int b = n >> 10, pos = n & 1023;
        const float* zr = z + (size_t)b * 262144 + pos;
        float zv[8];
        #pragma unroll
        for (int i = 0; i < 8; ++i)
            zv[i] = zr[(size_t)(lane + 32 * i) * 1024];
        double za = 0.0;
        #pragma unroll
        for (int i = 0; i < 8; ++i) za += (double)zv[i] * zv[i];
        #pragma unroll
        for (int o = 16; o; o >>= 1)
            za += __shfl_xor_sync(0xffffffffu, za, o);
        const float zn = (float)za;

        float bd = 3.4e38f;
        int   bi = 0x7fffffff;
        #pragma unroll 1
        for (int jb = 0; jb < 24; jb += 4) {
            int kc[4];
            float ac[4] = {0.f, 0.f, 0.f, 0.f};
            #pragma unroll
            for (int q = 0; q < 4; ++q) kc[q] = g_cand[r * 24 + jb + q];
            #pragma unroll
            for (int i = 0; i < 8; ++i) {
                #pragma unroll
                for (int q = 0; q < 4; ++q)
                    ac[q] = fmaf(zv[i], E[(size_t)kc[q] * 256 + lane + 32 * i],
                                 ac[q]);
            }
            #pragma unroll
            for (int o = 16; o; o >>= 1) {
                #pragma unroll
                for (int q = 0; q < 4; ++q)
                    ac[q] += __shfl_xor_sync(0xffffffffu, ac[q], o);
            }
            #pragma unroll
            for (int q = 0; q < 4; ++q) {
                float di = (zn - 2.0f * ac[q]) + g_enorm[kc[q]];
                if (di < bd || (di == bd && kc[q] < bi)) { bd = di; bi = kc[q]; }
            }
        }
        if (lane == 0) {
            g_indices[n] = bi;
            out[(size_t)OFF_IDX + n] = (float)bi;
        }
    }
}

// ---------------------------------------------------------------------------
// Kernel 4: fused gather/scatter (R6 staging version).
// z_q_st = fl(z + fl(E[idx]-z)), ||z||^2 partial, float4 RED scatter, counts.
// ---------------------------------------------------------------------------
__global__ __launch_bounds__(256)
void k_gather(const float* __restrict__ z, const float* __restrict__ E,
              float* __restrict__ out) {
    __shared__ float es[32 * 260];
    __shared__ int   sidx[32];
    __shared__ float ws[8];
    const int t   = threadIdx.x;
    const int n0  = blockIdx.x * 32;     // grid 1024
    const int b   = n0 >> 10;
    const int rem = n0 & 1023;

    if (t < 32) {
        int k = g_indices[n0 + t];
        sidx[t] = k;
        atomicAdd(&g_counts[k], 1.0f);
    }
    __syncthreads();

    #pragma unroll
    for (int k = 0; k < 32; ++k)
        es[k * 260 + t] = E[(size_t)sidx[k] * 256 + t];
    __syncthreads();

    const float* zb = z   + (size_t)b * 262144 + rem;
    float*       qb = out + (size_t)b * 262144 + rem;

    float zs = 0.f;
    #pragma unroll 2
    for (int it = 0; it < 8; ++it) {
        int idx = t + it * 256;          // 0..2047
        int nl  = idx & 31;
        int d4  = idx >> 5;              // 0..63
        int d   = d4 << 2;
        float4 e = *(const float4*)&es[nl * 260 + d];
        float z0 = zb[(size_t)(d + 0) * 1024 + nl];
        float z1 = zb[(size_t)(d + 1) * 1024 + nl];
        float z2 = zb[(size_t)(d + 2) * 1024 + nl];
        float z3 = zb[(size_t)(d + 3) * 1024 + nl];
        qb[(size_t)(d + 0) * 1024 + nl] = z0 + (e.x - z0);
        qb[(size_t)(d + 1) * 1024 + nl] = z1 + (e.y - z1);
        qb[(size_t)(d + 2) * 1024 + nl] = z2 + (e.z - z2);
        qb[(size_t)(d + 3) * 1024 + nl] = z3 + (e.w - z3);
        zs += z0 * z0 + z1 * z1 + z2 * z2 + z3 * z3;
        atomicAdd(&g_embed_sum4[(size_t)sidx[nl] * 64 + d4],
                  make_float4(z0, z1, z2, z3));
    }
    #pragma unroll
    for (int o = 16; o; o >>= 1) zs += __shfl_down_sync(0xffffffffu, zs, o);
    if ((t & 31) == 0) ws[t >> 5] = zs;
    __syncthreads();
    if (t == 0) {
        float tot = 0.f;
        #pragma unroll
        for (int i = 0; i < 8; ++i) tot += ws[i];
        atomicAdd(&g_loss_zn, tot);
    }
}

// ---------------------------------------------------------------------------
// Kernel 5: merged EMA epilogue.
// ---------------------------------------------------------------------------
__global__ __launch_bounds__(1024)
void k_emb(const float* __restrict__ cs_in, const float* __restrict__ es_in,
           float* __restrict__ out) {
    __shared__ float s_n;
    const int tid = threadIdx.x;
    const int i = blockIdx.x * 1024 + tid;   // grid 256 -> 262144

    if (tid < 32) {
        float s = 0.f;
        #pragma unroll
        for (int j = 0; j < 32; ++j) s += cs_in[tid + j * 32];
        #pragma unroll
        for (int o = 16; o; o >>= 1) s += __shfl_xor_sync(0xffffffffu, s, o);
        if (tid == 0) s_n = 0.99f * s + 327.68f;
    }
    __syncthreads();

    const int k = i >> 8;
    float c = 0.99f * cs_in[k] + 0.01f * g_counts[k];
    if ((i & 255) == 0) out[(size_t)OFF_CS + k] = c;
    float n  = s_n;
    float cl = (c + 1e-5f) / (n + 0.01024f) * n;
    float es = 0.99f * es_in[i] + 0.01f * ((const float*)g_embed_sum4)[i];
    out[(size_t)OFF_ES  + i] = es;
    out[(size_t)OFF_EMB + i] = es / cl;
    if (i == 0)
        out[OFF_LOSS] = (g_loss_zn + g_loss_sc) * (1.0f / 8388608.0f);
}

// ---------------------------------------------------------------------------
extern "C" void kernel_launch(void* const* d_in, const int* in_sizes, int n_in,
                              void* d_out, int out_size) {
    const float* z  = (const float*)d_in[0];
    const float* E  = (const float*)d_in[1];
    const float* cs = (const float*)d_in[2];
    const float* es = (const float*)d_in[3];
    float* out = (float*)d_out;

    cudaFuncSetAttribute(k_mma, cudaFuncAttributeMaxDynamicSharedMemorySize,
                         SMEM_MMA_TOTAL);

    k_init  <<<1024, 256>>>(E, out);
    k_mma   <<< 256, 256, SMEM_MMA_TOTAL>>>(z, out);
    k_fix   <<< 256, 256>>>(z, E, out);
    k_gather<<<1024, 256>>>(z, E, out);
    k_emb   <<< 256, 1024>>>(cs, es, out);
}